// round 5
// baseline (speedup 1.0000x reference)
#include <cuda_runtime.h>
#include <math.h>

#define Bn 64
#define Dn 256
#define Hn 512
#define Rn 32
#define CLIPV 50.0f
#define TB1 16   // batches per P1 block

// Output layout (concatenation of the returned tuple, fp32):
//   v_new      [64,512]      @ 0
//   new_h      [64,512]      @ 32768
//   dU_new     [64,512,512]  @ 65536
//   new_trace_e[64,512]      @ 16842752
//   new_trace_E[64,512,512]  @ 16875520
#define OFF_V    ((size_t)0)
#define OFF_NH   ((size_t)32768)
#define OFF_DU   ((size_t)65536)
#define OFF_TEO  ((size_t)16842752)
#define OFF_TEE  ((size_t)16875520)

// Device-global scratch (allocation-free)
__device__ float g_up[Hn * Hn];
__device__ float g_lo[Hn * Hn];
__device__ float g_suMod[Bn];
__device__ float g_sE;
__device__ float g_omU;

__device__ __forceinline__ float sigmoidf_(float x) {
    return 1.0f / (1.0f + expf(-x));
}

// ---------------------------------------------------------------------------
// P1: grid (128, 5).
//  y < 4 : warp-per-(i,b) row reduction over dU (2 rows in flight),
//          + clip-bound fold (y==0 only).
//  y == 4: 64 blocks (bx<64) compute g_suMod[b] for b=bx — the "mod"
//          gate-row reduction. These blocks run concurrently with the main
//          wave and finish much earlier, so the old 8.7us mod kernel
//          becomes free.
// ---------------------------------------------------------------------------
__global__ __launch_bounds__(128) void p1_kernel(
    const float* __restrict__ x, const float* __restrict__ h,
    const float* __restrict__ v, const float* __restrict__ dU,
    const float* __restrict__ trace_e, const float* __restrict__ x2h_w,
    const float* __restrict__ x2h_b, const float* __restrict__ h2h_w,
    const float* __restrict__ h2h_b, const float* __restrict__ alpha,
    const float* __restrict__ tau_v, const float* __restrict__ tau_e,
    const float* __restrict__ tau_U, const float* __restrict__ tau_E,
    float* __restrict__ out) {
    const int warp = threadIdx.x >> 5;
    const int lane = threadIdx.x & 31;

    if (blockIdx.y == 4) {
        // ---- mod slice ----
        const int b = blockIdx.x;
        if (b >= Bn) return;
        __shared__ float sm[4];

        const float4* xb = (const float4*)(x + (size_t)b * Dn);
        const float4* hb = (const float4*)(h + (size_t)b * Hn);

        float acc = 0.f;
#pragma unroll
        for (int t = 0; t < 8; t++) {
            const int r = warp + 4 * t;          // 4 warps x 8 rows = 32
            const int o = Hn + r;
            const float4* xw = (const float4*)(x2h_w + (size_t)o * Dn);
            const float4* hw = (const float4*)(h2h_w + (size_t)o * Hn);
            float s = 0.f;
#pragma unroll
            for (int c = 0; c < 2; c++) {
                const float4 W4 = xw[c * 32 + lane];
                const float4 V4 = xb[c * 32 + lane];
                s = fmaf(W4.x, V4.x, s); s = fmaf(W4.y, V4.y, s);
                s = fmaf(W4.z, V4.z, s); s = fmaf(W4.w, V4.w, s);
            }
#pragma unroll
            for (int c = 0; c < 4; c++) {
                const float4 W4 = hw[c * 32 + lane];
                const float4 V4 = hb[c * 32 + lane];
                s = fmaf(W4.x, V4.x, s); s = fmaf(W4.y, V4.y, s);
                s = fmaf(W4.z, V4.z, s); s = fmaf(W4.w, V4.w, s);
            }
#pragma unroll
            for (int off = 16; off; off >>= 1)
                s += __shfl_xor_sync(0xffffffffu, s, off);
            if (lane == 0) acc += fmaxf(s + x2h_b[o] + h2h_b[o], 0.f);
        }
        if (lane == 0) sm[warp] = acc;
        __syncthreads();
        if (threadIdx.x == 0) {
            const float m  = sm[0] + sm[1] + sm[2] + sm[3];
            const float sU = sigmoidf_(tau_U[0]);
            g_suMod[b] = sU * m;
            if (b == 0) {
                g_sE  = sigmoidf_(tau_E[0]);
                g_omU = 1.0f - sU;
            }
        }
        return;
    }

    // ---- main reduction slice ----
    const int i  = blockIdx.x * 4 + warp;
    const int b0 = blockIdx.y * TB1;
    const int jb = lane * 4;

    __shared__ float sh_h[TB1][Hn];
    __shared__ float sh_x[TB1][Dn];

    for (int idx = threadIdx.x; idx < TB1 * (Hn / 4); idx += 128) {
        const int bb = idx >> 7;
        const int jj = (idx & 127) * 4;
        *(float4*)&sh_h[bb][jj] = *(const float4*)(h + (size_t)(b0 + bb) * Hn + jj);
    }
    for (int idx = threadIdx.x; idx < TB1 * (Dn / 4); idx += 128) {
        const int bb = idx >> 6;
        const int jj = (idx & 63) * 4;
        *(float4*)&sh_x[bb][jj] = *(const float4*)(x + (size_t)(b0 + bb) * Dn + jj);
    }
    __syncthreads();

    // Per-i rows in registers (lane covers 4 chunks of 4 cols)
    float ar[4][4], Wr[4][4];
#pragma unroll
    for (int c = 0; c < 4; c++) {
        const int j = c * 128 + jb;
        const float4 A = *(const float4*)(alpha + (size_t)i * Hn + j);
        const float4 W = *(const float4*)(h2h_w + (size_t)i * Hn + j);
        ar[c][0] = fmaxf(A.x, 0.f); ar[c][1] = fmaxf(A.y, 0.f);
        ar[c][2] = fmaxf(A.z, 0.f); ar[c][3] = fmaxf(A.w, 0.f);
        Wr[c][0] = W.x; Wr[c][1] = W.y; Wr[c][2] = W.z; Wr[c][3] = W.w;
    }

    // Fold the old prep kernel: one block column computes clip bounds.
    if (blockIdx.y == 0) {
#pragma unroll
        for (int c = 0; c < 4; c++) {
            const int j = c * 128 + jb;
            float4 up, lo;
            float* u = (float*)&up;
            float* l = (float*)&lo;
#pragma unroll
            for (int k = 0; k < 4; k++) {
                const float d = ar[c][k] + 1e-8f;
                u[k] =  fmaxf(CLIPV - Wr[c][k], 0.f) / d;
                l[k] = -fmaxf(CLIPV + Wr[c][k], 0.f) / d;
            }
            *(float4*)(g_up + (size_t)i * Hn + j) = up;
            *(float4*)(g_lo + (size_t)i * Hn + j) = lo;
        }
    }

    float xw[2][4];
#pragma unroll
    for (int c = 0; c < 2; c++) {
        const float4 X = *(const float4*)(x2h_w + (size_t)i * Dn + c * 128 + jb);
        xw[c][0] = X.x; xw[c][1] = X.y; xw[c][2] = X.z; xw[c][3] = X.w;
    }
    const float bias = x2h_b[i] + h2h_b[i];
    const float sv   = sigmoidf_(tau_v[i]);
    const float se   = sigmoidf_(tau_e[i]);

    for (int bb = 0; bb < TB1; bb += 2) {
        const int bA = b0 + bb;
        const int bB = b0 + bb + 1;
        const size_t rowA = ((size_t)bA * Hn + i) * Hn;
        const size_t rowB = ((size_t)bB * Hn + i) * Hn;

        // 8 independent row loads
        float4 duA[4], duB[4];
#pragma unroll
        for (int c = 0; c < 4; c++) {
            duA[c] = *(const float4*)(dU + rowA + c * 128 + jb);
            duB[c] = *(const float4*)(dU + rowB + c * 128 + jb);
        }

        float p = 0.f, q = 0.f;
#pragma unroll
        for (int c = 0; c < 4; c++) {
            const int j = c * 128 + jb;
            const float* dA = (const float*)&duA[c];
            const float* dB = (const float*)&duB[c];
            const float4 HA = *(const float4*)&sh_h[bb][j];
            const float4 HB = *(const float4*)&sh_h[bb + 1][j];
            p = fmaf(fmaf(ar[c][0], dA[0], Wr[c][0]), HA.x, p);
            q = fmaf(fmaf(ar[c][0], dB[0], Wr[c][0]), HB.x, q);
            p = fmaf(fmaf(ar[c][1], dA[1], Wr[c][1]), HA.y, p);
            q = fmaf(fmaf(ar[c][1], dB[1], Wr[c][1]), HB.y, q);
            p = fmaf(fmaf(ar[c][2], dA[2], Wr[c][2]), HA.z, p);
            q = fmaf(fmaf(ar[c][2], dB[2], Wr[c][2]), HB.z, q);
            p = fmaf(fmaf(ar[c][3], dA[3], Wr[c][3]), HA.w, p);
            q = fmaf(fmaf(ar[c][3], dB[3], Wr[c][3]), HB.w, q);
        }
#pragma unroll
        for (int c = 0; c < 2; c++) {
            const float4 XA = *(const float4*)&sh_x[bb][c * 128 + jb];
            const float4 XB = *(const float4*)&sh_x[bb + 1][c * 128 + jb];
            p = fmaf(xw[c][0], XA.x, p);  q = fmaf(xw[c][0], XB.x, q);
            p = fmaf(xw[c][1], XA.y, p);  q = fmaf(xw[c][1], XB.y, q);
            p = fmaf(xw[c][2], XA.z, p);  q = fmaf(xw[c][2], XB.z, q);
            p = fmaf(xw[c][3], XA.w, p);  q = fmaf(xw[c][3], XB.w, q);
        }
        // interleaved butterflies: two independent chains overlap
#pragma unroll
        for (int off = 16; off; off >>= 1) {
            p += __shfl_xor_sync(0xffffffffu, p, off);
            q += __shfl_xor_sync(0xffffffffu, q, off);
        }

        if (lane == 0) {
            {
                const float dv  = p + bias;
                const float vb  = v[(size_t)bA * Hn + i];
                const float vn  = fmaf(sv, dv - vb, vb);
                const float teo = trace_e[(size_t)bA * Hn + i];
                out[OFF_V   + (size_t)bA * Hn + i] = vn;
                out[OFF_NH  + (size_t)bA * Hn + i] = fmaxf(vn, 0.f);
                out[OFF_TEO + (size_t)bA * Hn + i] = fmaf(se, sh_h[bb][i] - teo, teo);
            }
            {
                const float dv  = q + bias;
                const float vb  = v[(size_t)bB * Hn + i];
                const float vn  = fmaf(sv, dv - vb, vb);
                const float teo = trace_e[(size_t)bB * Hn + i];
                out[OFF_V   + (size_t)bB * Hn + i] = vn;
                out[OFF_NH  + (size_t)bB * Hn + i] = fmaxf(vn, 0.f);
                out[OFF_TEO + (size_t)bB * Hn + i] = fmaf(se, sh_h[bb + 1][i] - teo, teo);
            }
        }
    }
}

// ---------------------------------------------------------------------------
// P2: pure streaming elementwise pass over the HxH matrices.
// trace_E via __ldcs (zero reuse) so it doesn't evict the L2-warm dU.
// ---------------------------------------------------------------------------
#define P2_BLOCKS 8192
#define P2_THREADS 256
#define P2_TOTAL  ((size_t)Bn * Hn * 128)
#define P2_HALF   (P2_TOTAL / 2)

__global__ __launch_bounds__(P2_THREADS) void p2_kernel(
    const float* __restrict__ dU, const float* __restrict__ trace_E,
    const float* __restrict__ h, const float* __restrict__ trace_e,
    float* __restrict__ out) {
    const size_t gid = (size_t)blockIdx.x * P2_THREADS + threadIdx.x;
    const float sE  = g_sE;
    const float omU = g_omU;

    const float4* dU4 = (const float4*)dU;
    const float4* tE4 = (const float4*)trace_E;
    const float4* h4p = (const float4*)h;
    const float4* te4p = (const float4*)trace_e;
    const float4* up4 = (const float4*)g_up;
    const float4* lo4 = (const float4*)g_lo;
    float4* outDU = (float4*)(out + OFF_DU);
    float4* outTE = (float4*)(out + OFF_TEE);

#pragma unroll
    for (int half = 0; half < 2; half++) {
        const size_t t = gid + (size_t)half * P2_HALF;
        const int j4  = (int)(t & 127);
        const size_t row = t >> 7;           // b*512 + i
        const int i = (int)(row & 511);
        const int b = (int)(row >> 9);

        const float4 du = dU4[t];
        const float4 tE = __ldcs(&tE4[t]);
        const float4 hh = h4p[((size_t)b << 7) + j4];
        const float4 te = te4p[((size_t)b << 7) + j4];
        const float4 up = up4[((size_t)i << 7) + j4];
        const float4 lo = lo4[((size_t)i << 7) + j4];
        const float nh  = __ldg(out + OFF_NH  + row);
        const float nte = __ldg(out + OFF_TEO + row);
        const float suMod = g_suMod[b];

        float4 tOut, dOut;
        {
            const float o = nh * te.x - nte * hh.x;
            tOut.x = fmaf(sE, o - tE.x, tE.x);
            dOut.x = fmaxf(fminf(fmaf(suMod, tOut.x, omU * du.x), up.x), lo.x);
        }
        {
            const float o = nh * te.y - nte * hh.y;
            tOut.y = fmaf(sE, o - tE.y, tE.y);
            dOut.y = fmaxf(fminf(fmaf(suMod, tOut.y, omU * du.y), up.y), lo.y);
        }
        {
            const float o = nh * te.z - nte * hh.z;
            tOut.z = fmaf(sE, o - tE.z, tE.z);
            dOut.z = fmaxf(fminf(fmaf(suMod, tOut.z, omU * du.z), up.z), lo.z);
        }
        {
            const float o = nh * te.w - nte * hh.w;
            tOut.w = fmaf(sE, o - tE.w, tE.w);
            dOut.w = fmaxf(fminf(fmaf(suMod, tOut.w, omU * du.w), up.w), lo.w);
        }
        __stcs(&outTE[t], tOut);
        __stcs(&outDU[t], dOut);
    }
}

extern "C" void kernel_launch(void* const* d_in, const int* in_sizes, int n_in,
                              void* d_out, int out_size) {
    const float* x       = (const float*)d_in[0];
    const float* h       = (const float*)d_in[1];
    const float* v       = (const float*)d_in[2];
    const float* dU      = (const float*)d_in[3];
    const float* trace_e = (const float*)d_in[4];
    const float* trace_E = (const float*)d_in[5];
    const float* x2h_w   = (const float*)d_in[6];
    const float* x2h_b   = (const float*)d_in[7];
    const float* h2h_w   = (const float*)d_in[8];
    const float* h2h_b   = (const float*)d_in[9];
    const float* alpha   = (const float*)d_in[10];
    const float* tau_v   = (const float*)d_in[11];
    const float* tau_e   = (const float*)d_in[12];
    const float* tau_U   = (const float*)d_in[13];
    const float* tau_E   = (const float*)d_in[14];
    float* out = (float*)d_out;

    dim3 g1(Hn / 4, 5);   // y<4: row reductions; y==4: mod slice
    p1_kernel<<<g1, 128>>>(x, h, v, dU, trace_e, x2h_w, x2h_b, h2h_w, h2h_b,
                           alpha, tau_v, tau_e, tau_U, tau_E, out);
    p2_kernel<<<P2_BLOCKS, P2_THREADS>>>(dU, trace_E, h, trace_e, out);
}

// round 6
// speedup vs baseline: 1.1721x; 1.1721x over previous
#include <cuda_runtime.h>
#include <math.h>

#define Bn 64
#define Dn 256
#define Hn 512
#define Rn 32
#define CLIPV 50.0f
#define TB1 16   // batches per P1 main block

// Output layout (concatenation of the returned tuple, fp32):
//   v_new      [64,512]      @ 0
//   new_h      [64,512]      @ 32768
//   dU_new     [64,512,512]  @ 65536
//   new_trace_e[64,512]      @ 16842752
//   new_trace_E[64,512,512]  @ 16875520
#define OFF_V    ((size_t)0)
#define OFF_NH   ((size_t)32768)
#define OFF_DU   ((size_t)65536)
#define OFF_TEO  ((size_t)16842752)
#define OFF_TEE  ((size_t)16875520)

// Device-global scratch (allocation-free)
__device__ float g_up[Hn * Hn];
__device__ float g_lo[Hn * Hn];
__device__ float g_suMod[Bn];
__device__ float g_sE;
__device__ float g_omU;

__device__ __forceinline__ float sigmoidf_(float x) {
    return 1.0f / (1.0f + expf(-x));
}

// ---------------------------------------------------------------------------
// P1: 1D grid of 576 blocks (<= 608 = 152 SMs x 4 blocks @48KB smem -> ONE
// wave; R5's (128,5)=640-block grid spilled to 2 waves and regressed).
//  bx < 512 : main slice. gx = bx & 127 -> i-group, gy = bx >> 7 -> b0.
//             Warp-per-(i,b) row reduction over dU, 2 rows in flight.
//             gy==0 blocks also fold in the clip-bound precompute.
//  bx >= 512: mod slice for b = bx - 512, runs concurrently inside the
//             main wave (finishes far earlier) -> costs zero wall-clock.
// ---------------------------------------------------------------------------
__global__ __launch_bounds__(128) void p1_kernel(
    const float* __restrict__ x, const float* __restrict__ h,
    const float* __restrict__ v, const float* __restrict__ dU,
    const float* __restrict__ trace_e, const float* __restrict__ x2h_w,
    const float* __restrict__ x2h_b, const float* __restrict__ h2h_w,
    const float* __restrict__ h2h_b, const float* __restrict__ alpha,
    const float* __restrict__ tau_v, const float* __restrict__ tau_e,
    const float* __restrict__ tau_U, const float* __restrict__ tau_E,
    float* __restrict__ out) {
    const int warp = threadIdx.x >> 5;
    const int lane = threadIdx.x & 31;

    // Shared at function scope; mod path reuses a corner of sh_h so static
    // smem stays exactly 48KB (the opt-in-free limit).
    __shared__ float sh_h[TB1][Hn];
    __shared__ float sh_x[TB1][Dn];

    if (blockIdx.x >= 512) {
        // ---- mod slice ----
        const int b = blockIdx.x - 512;
        float* sm = &sh_h[0][0];  // 4 floats reused as warp partials

        const float4* xb = (const float4*)(x + (size_t)b * Dn);
        const float4* hb = (const float4*)(h + (size_t)b * Hn);

        float acc = 0.f;
#pragma unroll
        for (int t = 0; t < 8; t++) {
            const int r = warp + 4 * t;          // 4 warps x 8 rows = 32
            const int o = Hn + r;
            const float4* xw = (const float4*)(x2h_w + (size_t)o * Dn);
            const float4* hw = (const float4*)(h2h_w + (size_t)o * Hn);
            float s = 0.f;
#pragma unroll
            for (int c = 0; c < 2; c++) {
                const float4 W4 = xw[c * 32 + lane];
                const float4 V4 = xb[c * 32 + lane];
                s = fmaf(W4.x, V4.x, s); s = fmaf(W4.y, V4.y, s);
                s = fmaf(W4.z, V4.z, s); s = fmaf(W4.w, V4.w, s);
            }
#pragma unroll
            for (int c = 0; c < 4; c++) {
                const float4 W4 = hw[c * 32 + lane];
                const float4 V4 = hb[c * 32 + lane];
                s = fmaf(W4.x, V4.x, s); s = fmaf(W4.y, V4.y, s);
                s = fmaf(W4.z, V4.z, s); s = fmaf(W4.w, V4.w, s);
            }
#pragma unroll
            for (int off = 16; off; off >>= 1)
                s += __shfl_xor_sync(0xffffffffu, s, off);
            if (lane == 0) acc += fmaxf(s + x2h_b[o] + h2h_b[o], 0.f);
        }
        if (lane == 0) sm[warp] = acc;
        __syncthreads();
        if (threadIdx.x == 0) {
            const float m  = sm[0] + sm[1] + sm[2] + sm[3];
            const float sU = sigmoidf_(tau_U[0]);
            g_suMod[b] = sU * m;
            if (b == 0) {
                g_sE  = sigmoidf_(tau_E[0]);
                g_omU = 1.0f - sU;
            }
        }
        return;
    }

    // ---- main reduction slice ----
    const int gx = blockIdx.x & 127;
    const int gy = blockIdx.x >> 7;
    const int i  = gx * 4 + warp;
    const int b0 = gy * TB1;
    const int jb = lane * 4;

    for (int idx = threadIdx.x; idx < TB1 * (Hn / 4); idx += 128) {
        const int bb = idx >> 7;
        const int jj = (idx & 127) * 4;
        *(float4*)&sh_h[bb][jj] = *(const float4*)(h + (size_t)(b0 + bb) * Hn + jj);
    }
    for (int idx = threadIdx.x; idx < TB1 * (Dn / 4); idx += 128) {
        const int bb = idx >> 6;
        const int jj = (idx & 63) * 4;
        *(float4*)&sh_x[bb][jj] = *(const float4*)(x + (size_t)(b0 + bb) * Dn + jj);
    }
    __syncthreads();

    // Per-i rows in registers (lane covers 4 chunks of 4 cols)
    float ar[4][4], Wr[4][4];
#pragma unroll
    for (int c = 0; c < 4; c++) {
        const int j = c * 128 + jb;
        const float4 A = *(const float4*)(alpha + (size_t)i * Hn + j);
        const float4 W = *(const float4*)(h2h_w + (size_t)i * Hn + j);
        ar[c][0] = fmaxf(A.x, 0.f); ar[c][1] = fmaxf(A.y, 0.f);
        ar[c][2] = fmaxf(A.z, 0.f); ar[c][3] = fmaxf(A.w, 0.f);
        Wr[c][0] = W.x; Wr[c][1] = W.y; Wr[c][2] = W.z; Wr[c][3] = W.w;
    }

    // Clip-bound fold: one block column computes up/lo.
    if (gy == 0) {
#pragma unroll
        for (int c = 0; c < 4; c++) {
            const int j = c * 128 + jb;
            float4 up, lo;
            float* u = (float*)&up;
            float* l = (float*)&lo;
#pragma unroll
            for (int k = 0; k < 4; k++) {
                const float d = ar[c][k] + 1e-8f;
                u[k] =  fmaxf(CLIPV - Wr[c][k], 0.f) / d;
                l[k] = -fmaxf(CLIPV + Wr[c][k], 0.f) / d;
            }
            *(float4*)(g_up + (size_t)i * Hn + j) = up;
            *(float4*)(g_lo + (size_t)i * Hn + j) = lo;
        }
    }

    float xw[2][4];
#pragma unroll
    for (int c = 0; c < 2; c++) {
        const float4 X = *(const float4*)(x2h_w + (size_t)i * Dn + c * 128 + jb);
        xw[c][0] = X.x; xw[c][1] = X.y; xw[c][2] = X.z; xw[c][3] = X.w;
    }
    const float bias = x2h_b[i] + h2h_b[i];
    const float sv   = sigmoidf_(tau_v[i]);
    const float se   = sigmoidf_(tau_e[i]);

    for (int bb = 0; bb < TB1; bb += 2) {
        const int bA = b0 + bb;
        const int bB = b0 + bb + 1;
        const size_t rowA = ((size_t)bA * Hn + i) * Hn;
        const size_t rowB = ((size_t)bB * Hn + i) * Hn;

        // 8 independent row loads
        float4 duA[4], duB[4];
#pragma unroll
        for (int c = 0; c < 4; c++) {
            duA[c] = *(const float4*)(dU + rowA + c * 128 + jb);
            duB[c] = *(const float4*)(dU + rowB + c * 128 + jb);
        }

        float p = 0.f, q = 0.f;
#pragma unroll
        for (int c = 0; c < 4; c++) {
            const int j = c * 128 + jb;
            const float* dA = (const float*)&duA[c];
            const float* dB = (const float*)&duB[c];
            const float4 HA = *(const float4*)&sh_h[bb][j];
            const float4 HB = *(const float4*)&sh_h[bb + 1][j];
            p = fmaf(fmaf(ar[c][0], dA[0], Wr[c][0]), HA.x, p);
            q = fmaf(fmaf(ar[c][0], dB[0], Wr[c][0]), HB.x, q);
            p = fmaf(fmaf(ar[c][1], dA[1], Wr[c][1]), HA.y, p);
            q = fmaf(fmaf(ar[c][1], dB[1], Wr[c][1]), HB.y, q);
            p = fmaf(fmaf(ar[c][2], dA[2], Wr[c][2]), HA.z, p);
            q = fmaf(fmaf(ar[c][2], dB[2], Wr[c][2]), HB.z, q);
            p = fmaf(fmaf(ar[c][3], dA[3], Wr[c][3]), HA.w, p);
            q = fmaf(fmaf(ar[c][3], dB[3], Wr[c][3]), HB.w, q);
        }
#pragma unroll
        for (int c = 0; c < 2; c++) {
            const float4 XA = *(const float4*)&sh_x[bb][c * 128 + jb];
            const float4 XB = *(const float4*)&sh_x[bb + 1][c * 128 + jb];
            p = fmaf(xw[c][0], XA.x, p);  q = fmaf(xw[c][0], XB.x, q);
            p = fmaf(xw[c][1], XA.y, p);  q = fmaf(xw[c][1], XB.y, q);
            p = fmaf(xw[c][2], XA.z, p);  q = fmaf(xw[c][2], XB.z, q);
            p = fmaf(xw[c][3], XA.w, p);  q = fmaf(xw[c][3], XB.w, q);
        }
        // interleaved butterflies: two independent chains overlap
#pragma unroll
        for (int off = 16; off; off >>= 1) {
            p += __shfl_xor_sync(0xffffffffu, p, off);
            q += __shfl_xor_sync(0xffffffffu, q, off);
        }

        if (lane == 0) {
            {
                const float dv  = p + bias;
                const float vb  = v[(size_t)bA * Hn + i];
                const float vn  = fmaf(sv, dv - vb, vb);
                const float teo = trace_e[(size_t)bA * Hn + i];
                out[OFF_V   + (size_t)bA * Hn + i] = vn;
                out[OFF_NH  + (size_t)bA * Hn + i] = fmaxf(vn, 0.f);
                out[OFF_TEO + (size_t)bA * Hn + i] = fmaf(se, sh_h[bb][i] - teo, teo);
            }
            {
                const float dv  = q + bias;
                const float vb  = v[(size_t)bB * Hn + i];
                const float vn  = fmaf(sv, dv - vb, vb);
                const float teo = trace_e[(size_t)bB * Hn + i];
                out[OFF_V   + (size_t)bB * Hn + i] = vn;
                out[OFF_NH  + (size_t)bB * Hn + i] = fmaxf(vn, 0.f);
                out[OFF_TEO + (size_t)bB * Hn + i] = fmaf(se, sh_h[bb + 1][i] - teo, teo);
            }
        }
    }
}

// ---------------------------------------------------------------------------
// P2: pure streaming elementwise pass over the HxH matrices.
// trace_E via __ldcs (zero reuse) so it doesn't evict the L2-warm dU.
// ---------------------------------------------------------------------------
#define P2_BLOCKS 8192
#define P2_THREADS 256
#define P2_TOTAL  ((size_t)Bn * Hn * 128)
#define P2_HALF   (P2_TOTAL / 2)

__global__ __launch_bounds__(P2_THREADS) void p2_kernel(
    const float* __restrict__ dU, const float* __restrict__ trace_E,
    const float* __restrict__ h, const float* __restrict__ trace_e,
    float* __restrict__ out) {
    const size_t gid = (size_t)blockIdx.x * P2_THREADS + threadIdx.x;
    const float sE  = g_sE;
    const float omU = g_omU;

    const float4* dU4 = (const float4*)dU;
    const float4* tE4 = (const float4*)trace_E;
    const float4* h4p = (const float4*)h;
    const float4* te4p = (const float4*)trace_e;
    const float4* up4 = (const float4*)g_up;
    const float4* lo4 = (const float4*)g_lo;
    float4* outDU = (float4*)(out + OFF_DU);
    float4* outTE = (float4*)(out + OFF_TEE);

#pragma unroll
    for (int half = 0; half < 2; half++) {
        const size_t t = gid + (size_t)half * P2_HALF;
        const int j4  = (int)(t & 127);
        const size_t row = t >> 7;           // b*512 + i
        const int i = (int)(row & 511);
        const int b = (int)(row >> 9);

        const float4 du = dU4[t];
        const float4 tE = __ldcs(&tE4[t]);
        const float4 hh = h4p[((size_t)b << 7) + j4];
        const float4 te = te4p[((size_t)b << 7) + j4];
        const float4 up = up4[((size_t)i << 7) + j4];
        const float4 lo = lo4[((size_t)i << 7) + j4];
        const float nh  = __ldg(out + OFF_NH  + row);
        const float nte = __ldg(out + OFF_TEO + row);
        const float suMod = g_suMod[b];

        float4 tOut, dOut;
        {
            const float o = nh * te.x - nte * hh.x;
            tOut.x = fmaf(sE, o - tE.x, tE.x);
            dOut.x = fmaxf(fminf(fmaf(suMod, tOut.x, omU * du.x), up.x), lo.x);
        }
        {
            const float o = nh * te.y - nte * hh.y;
            tOut.y = fmaf(sE, o - tE.y, tE.y);
            dOut.y = fmaxf(fminf(fmaf(suMod, tOut.y, omU * du.y), up.y), lo.y);
        }
        {
            const float o = nh * te.z - nte * hh.z;
            tOut.z = fmaf(sE, o - tE.z, tE.z);
            dOut.z = fmaxf(fminf(fmaf(suMod, tOut.z, omU * du.z), up.z), lo.z);
        }
        {
            const float o = nh * te.w - nte * hh.w;
            tOut.w = fmaf(sE, o - tE.w, tE.w);
            dOut.w = fmaxf(fminf(fmaf(suMod, tOut.w, omU * du.w), up.w), lo.w);
        }
        __stcs(&outTE[t], tOut);
        __stcs(&outDU[t], dOut);
    }
}

extern "C" void kernel_launch(void* const* d_in, const int* in_sizes, int n_in,
                              void* d_out, int out_size) {
    const float* x       = (const float*)d_in[0];
    const float* h       = (const float*)d_in[1];
    const float* v       = (const float*)d_in[2];
    const float* dU      = (const float*)d_in[3];
    const float* trace_e = (const float*)d_in[4];
    const float* trace_E = (const float*)d_in[5];
    const float* x2h_w   = (const float*)d_in[6];
    const float* x2h_b   = (const float*)d_in[7];
    const float* h2h_w   = (const float*)d_in[8];
    const float* h2h_b   = (const float*)d_in[9];
    const float* alpha   = (const float*)d_in[10];
    const float* tau_v   = (const float*)d_in[11];
    const float* tau_e   = (const float*)d_in[12];
    const float* tau_U   = (const float*)d_in[13];
    const float* tau_E   = (const float*)d_in[14];
    float* out = (float*)d_out;

    p1_kernel<<<576, 128>>>(x, h, v, dU, trace_e, x2h_w, x2h_b, h2h_w, h2h_b,
                            alpha, tau_v, tau_e, tau_U, tau_E, out);
    p2_kernel<<<P2_BLOCKS, P2_THREADS>>>(dU, trace_E, h, trace_e, out);
}